// round 12
// baseline (speedup 1.0000x reference)
#include <cuda_runtime.h>
#include <math.h>

#define EPSF 1e-5f

// Re-laid-out weights: Wt4[B][g][C] (float4), g = jk/4.
__device__ float4 Wt4_buf[288 * 4 * 32];

__global__ void transpose_W_kernel(const float* __restrict__ Wg) {
    int idx = blockIdx.x * 256 + threadIdx.x;
    if (idx >= 288 * 16 * 32) return;
    int q = idx & 3;
    int C = (idx >> 2) & 31;
    int g = (idx >> 7) & 3;
    int B = idx >> 9;
    ((float*)Wt4_buf)[idx] = Wg[((B << 5) + C) * 16 + (g << 2) + q];
}

typedef unsigned long long u64;

// packed f32x2 helpers
#define PACK2(d, s)      asm("mov.b64 %0, {%1, %1};" : "=l"(d) : "f"(s))
#define UNPK2(lo, hi, s) asm("mov.b64 {%0, %1}, %2;" : "=f"(lo), "=f"(hi) : "l"(s))
#define FMA2(d, a, b, c) asm("fma.rn.f32x2 %0, %1, %2, %3;" : "=l"(d) : "l"(a), "l"(b), "l"(c))
#define MUL2(d, a, b)    asm("mul.rn.f32x2 %0, %1, %2;" : "=l"(d) : "l"(a), "l"(b))
#define ADD2(d, a, b)    asm("add.rn.f32x2 %0, %1, %2;" : "=l"(d) : "l"(a), "l"(b))

// SMEM layout (float indices):
//  Xs2  [288*16 u64]  = 9216 floats  @0      (X pre-packed as {x,x} pairs)
//  vbuf [8*32*16]     = 4096         @9216
//  vcur [32*16]       = 512          @13312
//  invd [32]          = 32           @13824
//  mred [8*32]        = 256          @13856
//  nred [8*32]        = 256          @14112
#define SMEM_FLOATS 14368

// p_out has 4*32*16*8*8 = 131072 elements; a_out follows it.
#define AOUT_BASE 131072

#define LOADW(B, wa0, wb0, wa1, wb1, wa2, wb2, wa3, wb3)                       \
    {                                                                          \
        const ulonglong2* Wp_ =                                                \
            reinterpret_cast<const ulonglong2*>(Wt4_buf) + ((B) << 7) + lane;  \
        ulonglong2 t0 = Wp_[0], t1 = Wp_[32], t2 = Wp_[64], t3 = Wp_[96];      \
        wa0 = t0.x; wb0 = t0.y; wa1 = t1.x; wb1 = t1.y;                        \
        wa2 = t2.x; wb2 = t2.y; wa3 = t3.x; wb3 = t3.y;                        \
    }

// L1 prefetch of W[B]'s 2KB region (32 lanes x 64B covers all 16 lines).
#define PREFW(B)                                                               \
    asm volatile("prefetch.global.L1 [%0];" ::                                 \
        "l"((const char*)(Wt4_buf + ((B) << 7)) + (lane << 6)));

// u[16] = X[B] (4x4) @ W (packed regs). X read pre-packed from smem (LDS.64
// broadcasts) -> no per-iteration pack MOVs. 8 packed u64 results.
#define COMPUTE_U_P(B, wa0, wb0, wa1, wb1, wa2, wb2, wa3, wb3,                 \
                    ua0, ub0, ua1, ub1, ua2, ub2, ua3, ub3)                    \
    {                                                                          \
        const u64* Xp = X2 + ((B) << 4);                                       \
        u64 xp0 = Xp[0],  xp1 = Xp[1],  xp2 = Xp[2],  xp3 = Xp[3];             \
        MUL2(ua0, xp0, wa0); MUL2(ub0, xp0, wb0);                              \
        FMA2(ua0, xp1, wa1, ua0); FMA2(ub0, xp1, wb1, ub0);                    \
        FMA2(ua0, xp2, wa2, ua0); FMA2(ub0, xp2, wb2, ub0);                    \
        FMA2(ua0, xp3, wa3, ua0); FMA2(ub0, xp3, wb3, ub0);                    \
        u64 xq0 = Xp[4],  xq1 = Xp[5],  xq2 = Xp[6],  xq3 = Xp[7];             \
        MUL2(ua1, xq0, wa0); MUL2(ub1, xq0, wb0);                              \
        FMA2(ua1, xq1, wa1, ua1); FMA2(ub1, xq1, wb1, ub1);                    \
        FMA2(ua1, xq2, wa2, ua1); FMA2(ub1, xq2, wb2, ub1);                    \
        FMA2(ua1, xq3, wa3, ua1); FMA2(ub1, xq3, wb3, ub1);                    \
        u64 xr0 = Xp[8],  xr1 = Xp[9],  xr2 = Xp[10], xr3 = Xp[11];            \
        MUL2(ua2, xr0, wa0); MUL2(ub2, xr0, wb0);                              \
        FMA2(ua2, xr1, wa1, ua2); FMA2(ub2, xr1, wb1, ub2);                    \
        FMA2(ua2, xr2, wa2, ua2); FMA2(ub2, xr2, wb2, ub2);                    \
        FMA2(ua2, xr3, wa3, ua2); FMA2(ub2, xr3, wb3, ub2);                    \
        u64 xs0 = Xp[12], xs1 = Xp[13], xs2 = Xp[14], xs3 = Xp[15];            \
        MUL2(ua3, xs0, wa0); MUL2(ub3, xs0, wb0);                              \
        FMA2(ua3, xs1, wa1, ua3); FMA2(ub3, xs1, wb1, ub3);                    \
        FMA2(ua3, xs2, wa2, ua3); FMA2(ub3, xs2, wb2, ub3);                    \
        FMA2(ua3, xs3, wa3, ua3); FMA2(ub3, xs3, wb3, ub3);                    \
    }

// packed elementwise dot of 8 pairs -> scalar (lo+hi)
#define PDOT8(res, ua0, ub0, ua1, ub1, ua2, ub2, ua3, ub3,                     \
              va0, vb0, va1, vb1, va2, vb2, va3, vb3)                          \
    {                                                                          \
        u64 t_;                                                                \
        MUL2(t_, ua0, va0); FMA2(t_, ub0, vb0, t_);                            \
        FMA2(t_, ua1, va1, t_); FMA2(t_, ub1, vb1, t_);                        \
        FMA2(t_, ua2, va2, t_); FMA2(t_, ub2, vb2, t_);                        \
        FMA2(t_, ua3, va3, t_); FMA2(t_, ub3, vb3, t_);                        \
        float lo_, hi_;                                                        \
        UNPK2(lo_, hi_, t_);                                                   \
        res = lo_ + hi_;                                                       \
    }

__global__ __launch_bounds__(256, 2)
void convcaps_kernel(const float* __restrict__ x,
                     float* __restrict__ out) {
    extern __shared__ float smem[];
    const u64* X2 = reinterpret_cast<const u64*>(smem);
    float* vbuf = smem + 9216;
    float* vcur = smem + 13312;
    float* invd = smem + 13824;
    float* mred = smem + 13856;
    float* nred = smem + 14112;

    const int tid  = threadIdx.x;
    const int lane = tid & 31;     // = C
    const int wp   = tid >> 5;     // warp id, B ≡ wp (mod 8)
    const int pos  = blockIdx.x;   // b*64 + h*8 + w
    const int b    = pos >> 6;
    const int hw   = pos & 63;
    const int h    = hw >> 3;
    const int w    = hw & 7;

    // ---- gather patch poses, stored PRE-PACKED as {x,x} f32x2 pairs ----
    {
        float2* X2w = reinterpret_cast<float2*>(smem);
        for (int idx = tid; idx < 4608; idx += 256) {
            int B_ = idx >> 4, p = idx & 15;
            int Bcap = B_ / 9;
            int kk = B_ - Bcap * 9;
            int ki = kk / 3, kj = kk - ki * 3;
            int hh = 2 * h + ki - 1, ww = 2 * w + kj - 1;
            float val = 0.f;
            if ((unsigned)hh < 16u && (unsigned)ww < 16u)
                val = x[(((b * 32 + Bcap) * 16 + p) << 8) + (hh << 4) + ww];
            X2w[idx] = make_float2(val, val);
        }
    }
    __syncthreads();

    float4*       vbufv  = reinterpret_cast<float4*>(vbuf);
    float4*       vcurv  = reinterpret_cast<float4*>(vcur);
    ulonglong2*   vbufp  = reinterpret_cast<ulonglong2*>(vbuf);
    const ulonglong2* vcurp = reinterpret_cast<const ulonglong2*>(vcur);

    u64 aa0, ab0, aa1, ab1, aa2, ab2, aa3, ab3;

    // ================= PASS A: norms (for max-min) + uniform sum ==========
    {
        float mx = -3.4e38f, mn = 3.4e38f;
        u64 z = 0;
        aa0 = ab0 = aa1 = ab1 = aa2 = ab2 = aa3 = ab3 = z;
        u64 wa0, wb0, wa1, wb1, wa2, wb2, wa3, wb3;
        LOADW(wp, wa0, wb0, wa1, wb1, wa2, wb2, wa3, wb3)
        PREFW(wp + 8)
        #pragma unroll 2
        for (int k = 0; k < 36; k++) {
            int B  = wp + (k << 3);
            int Bn = (k < 35) ? B + 8 : wp;
            u64 na0, nb0, na1, nb1, na2, nb2, na3, nb3;
            LOADW(Bn, na0, nb0, na1, nb1, na2, nb2, na3, nb3)   // dist-1 regs
            PREFW((k < 34) ? B + 16 : wp)                       // dist-2 L1
            u64 ua0, ub0, ua1, ub1, ua2, ub2, ua3, ub3;
            COMPUTE_U_P(B, wa0, wb0, wa1, wb1, wa2, wb2, wa3, wb3,
                           ua0, ub0, ua1, ub1, ua2, ub2, ua3, ub3)
            float ss;
            PDOT8(ss, ua0, ub0, ua1, ub1, ua2, ub2, ua3, ub3,
                      ua0, ub0, ua1, ub1, ua2, ub2, ua3, ub3)
            float nrm = __fsqrt_rn(ss + EPSF);
            mx = fmaxf(mx, nrm);
            mn = fminf(mn, nrm);
            ADD2(aa0, aa0, ua0); ADD2(ab0, ab0, ub0);
            ADD2(aa1, aa1, ua1); ADD2(ab1, ab1, ub1);
            ADD2(aa2, aa2, ua2); ADD2(ab2, ab2, ub2);
            ADD2(aa3, aa3, ua3); ADD2(ab3, ab3, ub3);
            wa0 = na0; wb0 = nb0; wa1 = na1; wb1 = nb1;
            wa2 = na2; wb2 = nb2; wa3 = na3; wb3 = nb3;
        }
        mred[(wp << 5) + lane] = mx;
        nred[(wp << 5) + lane] = mn;
        int base = ((wp << 5) + lane) << 2;
        ulonglong2 s0; s0.x = aa0; s0.y = ab0; vbufp[base + 0] = s0;
        ulonglong2 s1; s1.x = aa1; s1.y = ab1; vbufp[base + 1] = s1;
        ulonglong2 s2; s2.x = aa2; s2.y = ab2; vbufp[base + 2] = s2;
        ulonglong2 s3; s3.x = aa3; s3.y = ab3; vbufp[base + 3] = s3;
    }
    __syncthreads();
    if (tid < 32) {
        float M = -3.4e38f, m = 3.4e38f;
        #pragma unroll
        for (int k = 0; k < 8; k++) {
            M = fmaxf(M, mred[(k << 5) + tid]);
            m = fminf(m, nred[(k << 5) + tid]);
        }
        invd[tid] = 1.f / (M - m);
    }
    __syncthreads();
    // reduce across warps + squash -> v0
    if (tid < 128) {
        int C = tid >> 2;
        float4 acc = vbufv[tid];
        #pragma unroll
        for (int k = 1; k < 8; k++) {
            float4 t = vbufv[(k << 7) + tid];
            acc.x += t.x; acc.y += t.y; acc.z += t.z; acc.w += t.w;
        }
        float f = invd[C] * (1.f / 32.f);
        acc.x *= f; acc.y *= f; acc.z *= f; acc.w *= f;
        float s = acc.x * acc.x + acc.y * acc.y + acc.z * acc.z + acc.w * acc.w;
        s += __shfl_xor_sync(0xffffffffu, s, 1);
        s += __shfl_xor_sync(0xffffffffu, s, 2);
        float nrm = __fsqrt_rn(s + EPSF);
        float g = 1.f / (1.f + nrm);
        acc.x *= g; acc.y *= g; acc.z *= g; acc.w *= g;
        vcurv[tid] = acc;
    }
    __syncthreads();

    const float invd_c = invd[lane];

    // v0 packed, kept in registers (pass C uses v0+v1 by linearity)
    u64 va0, vb0, va1, vb1, va2, vb2, va3, vb3;
    {
        ulonglong2 t0 = vcurp[(lane << 2) + 0];
        ulonglong2 t1 = vcurp[(lane << 2) + 1];
        ulonglong2 t2 = vcurp[(lane << 2) + 2];
        ulonglong2 t3 = vcurp[(lane << 2) + 3];
        va0 = t0.x; vb0 = t0.y; va1 = t1.x; vb1 = t1.y;
        va2 = t2.x; vb2 = t2.y; va3 = t3.x; vb3 = t3.y;
    }

// Routing pass body (R9 rotate-prefetch structure + dist-2 L1 prefetch).
#define ROUTING_PASS_LOOP                                                      \
    {                                                                          \
        u64 wa0, wb0, wa1, wb1, wa2, wb2, wa3, wb3;                            \
        LOADW(wp, wa0, wb0, wa1, wb1, wa2, wb2, wa3, wb3)                      \
        PREFW(wp + 8)                                                          \
        _Pragma("unroll 2")                                                    \
        for (int k = 0; k < 36; k++) {                                         \
            int B  = wp + (k << 3);                                            \
            int Bn = (k < 35) ? B + 8 : wp;                                    \
            u64 na0, nb0, na1, nb1, na2, nb2, na3, nb3;                        \
            LOADW(Bn, na0, nb0, na1, nb1, na2, nb2, na3, nb3)                  \
            PREFW((k < 34) ? B + 16 : wp)                                      \
            u64 ua0, ub0, ua1, ub1, ua2, ub2, ua3, ub3;                        \
            COMPUTE_U_P(B, wa0, wb0, wa1, wb1, wa2, wb2, wa3, wb3,             \
                           ua0, ub0, ua1, ub1, ua2, ub2, ua3, ub3)             \
            float dt;                                                          \
            PDOT8(dt, ua0, ub0, ua1, ub1, ua2, ub2, ua3, ub3,                  \
                      va0, vb0, va1, vb1, va2, vb2, va3, vb3)                  \
            float e = __expf(dt * invd_c);                                     \
            float s = e;                                                       \
            _Pragma("unroll")                                                  \
            for (int o = 16; o > 0; o >>= 1)                                   \
                s += __shfl_xor_sync(0xffffffffu, s, o);                       \
            float c = __fdividef(e, s);                                        \
            u64 cP; PACK2(cP, c);                                              \
            FMA2(aa0, cP, ua0, aa0); FMA2(ab0, cP, ub0, ab0);                  \
            FMA2(aa1, cP, ua1, aa1); FMA2(ab1, cP, ub1, ab1);                  \
            FMA2(aa2, cP, ua2, aa2); FMA2(ab2, cP, ub2, ab2);                  \
            FMA2(aa3, cP, ua3, aa3); FMA2(ab3, cP, ub3, ab3);                  \
            wa0 = na0; wb0 = nb0; wa1 = na1; wb1 = nb1;                        \
            wa2 = na2; wb2 = nb2; wa3 = na3; wb3 = nb3;                        \
        }                                                                      \
    }

    // ================= PASS B: r1 = u.v0, c1 = softmax_C, accum c1*u ======
    {
        u64 z = 0;
        aa0 = ab0 = aa1 = ab1 = aa2 = ab2 = aa3 = ab3 = z;
        ROUTING_PASS_LOOP
        int base = ((wp << 5) + lane) << 2;
        ulonglong2 s0; s0.x = aa0; s0.y = ab0; vbufp[base + 0] = s0;
        ulonglong2 s1; s1.x = aa1; s1.y = ab1; vbufp[base + 1] = s1;
        ulonglong2 s2; s2.x = aa2; s2.y = ab2; vbufp[base + 2] = s2;
        ulonglong2 s3; s3.x = aa3; s3.y = ab3; vbufp[base + 3] = s3;
    }
    __syncthreads();
    if (tid < 128) {
        int C = tid >> 2;
        float4 acc = vbufv[tid];
        #pragma unroll
        for (int k = 1; k < 8; k++) {
            float4 t = vbufv[(k << 7) + tid];
            acc.x += t.x; acc.y += t.y; acc.z += t.z; acc.w += t.w;
        }
        float f = invd[C];
        acc.x *= f; acc.y *= f; acc.z *= f; acc.w *= f;
        float s = acc.x * acc.x + acc.y * acc.y + acc.z * acc.z + acc.w * acc.w;
        s += __shfl_xor_sync(0xffffffffu, s, 1);
        s += __shfl_xor_sync(0xffffffffu, s, 2);
        float nrm = __fsqrt_rn(s + EPSF);
        float g = 1.f / (1.f + nrm);
        acc.x *= g; acc.y *= g; acc.z *= g; acc.w *= g;
        vcurv[tid] = acc;   // v1
    }
    __syncthreads();

    // vl = v0 + v1 (linearity: r2 = r1 + u.v1*invd = invd * u.(v0+v1))
    {
        ulonglong2 t0 = vcurp[(lane << 2) + 0];
        ulonglong2 t1 = vcurp[(lane << 2) + 1];
        ulonglong2 t2 = vcurp[(lane << 2) + 2];
        ulonglong2 t3 = vcurp[(lane << 2) + 3];
        ADD2(va0, va0, t0.x); ADD2(vb0, vb0, t0.y);
        ADD2(va1, va1, t1.x); ADD2(vb1, vb1, t1.y);
        ADD2(va2, va2, t2.x); ADD2(vb2, vb2, t2.y);
        ADD2(va3, va3, t3.x); ADD2(vb3, vb3, t3.y);
    }

    // ================= PASS C: r2 = invd*u.(v0+v1), c2, accum, output ======
    {
        u64 z = 0;
        aa0 = ab0 = aa1 = ab1 = aa2 = ab2 = aa3 = ab3 = z;
        ROUTING_PASS_LOOP
        int base = ((wp << 5) + lane) << 2;
        ulonglong2 s0; s0.x = aa0; s0.y = ab0; vbufp[base + 0] = s0;
        ulonglong2 s1; s1.x = aa1; s1.y = ab1; vbufp[base + 1] = s1;
        ulonglong2 s2; s2.x = aa2; s2.y = ab2; vbufp[base + 2] = s2;
        ulonglong2 s3; s3.x = aa3; s3.y = ab3; vbufp[base + 3] = s3;
    }
    __syncthreads();
    if (tid < 128) {
        int C = tid >> 2, q = tid & 3;
        float4 acc = vbufv[tid];
        #pragma unroll
        for (int k = 1; k < 8; k++) {
            float4 t = vbufv[(k << 7) + tid];
            acc.x += t.x; acc.y += t.y; acc.z += t.z; acc.w += t.w;
        }
        float f = invd[C];
        acc.x *= f; acc.y *= f; acc.z *= f; acc.w *= f;
        float s = acc.x * acc.x + acc.y * acc.y + acc.z * acc.z + acc.w * acc.w;
        s += __shfl_xor_sync(0xffffffffu, s, 1);
        s += __shfl_xor_sync(0xffffffffu, s, 2);
        float nrm = __fsqrt_rn(s + EPSF);
        float g = 1.f / (1.f + nrm);
        acc.x *= g; acc.y *= g; acc.z *= g; acc.w *= g;   // v2 (p_out)
        float s2 = acc.x * acc.x + acc.y * acc.y + acc.z * acc.z + acc.w * acc.w;
        s2 += __shfl_xor_sync(0xffffffffu, s2, 1);
        s2 += __shfl_xor_sync(0xffffffffu, s2, 2);
        float aout = __fsqrt_rn(s2 + EPSF);               // a_out = safe_norm(v2)
        int basep = (((b * 32 + C) * 16 + (q << 2)) << 6) + hw;
        out[basep]       = acc.x;
        out[basep + 64]  = acc.y;
        out[basep + 128] = acc.z;
        out[basep + 192] = acc.w;
        if (q == 0)
            out[AOUT_BASE + ((b * 32 + C) << 6) + hw] = aout;
    }
}

extern "C" void kernel_launch(void* const* d_in, const int* in_sizes, int n_in,
                              void* d_out, int out_size) {
    (void)out_size;
    // Resolve inputs BY SIZE — immune to metadata ordering.
    const float* x  = nullptr;
    const float* Wg = nullptr;
    for (int i = 0; i < n_in; i++) {
        if (in_sizes[i] == 524288)      x  = (const float*)d_in[i];
        else if (in_sizes[i] == 147456) Wg = (const float*)d_in[i];
    }
    float* out = (float*)d_out;

    transpose_W_kernel<<<(288 * 16 * 32 + 255) / 256, 256>>>(Wg);

    const size_t smem_bytes = SMEM_FLOATS * sizeof(float);
    cudaFuncSetAttribute(convcaps_kernel,
                         cudaFuncAttributeMaxDynamicSharedMemorySize,
                         (int)smem_bytes);
    convcaps_kernel<<<256, 256, smem_bytes>>>(x, out);
}

// round 13
// speedup vs baseline: 1.0478x; 1.0478x over previous
#include <cuda_runtime.h>
#include <math.h>

#define EPSF 1e-5f

// Re-laid-out weights: Wt4[B][g][C] (float4), g = jk/4.
__device__ float4 Wt4_buf[288 * 4 * 32];

__global__ void transpose_W_kernel(const float* __restrict__ Wg) {
    int idx = blockIdx.x * 256 + threadIdx.x;
    if (idx >= 288 * 16 * 32) return;
    int q = idx & 3;
    int C = (idx >> 2) & 31;
    int g = (idx >> 7) & 3;
    int B = idx >> 9;
    ((float*)Wt4_buf)[idx] = Wg[((B << 5) + C) * 16 + (g << 2) + q];
}

typedef unsigned long long u64;

// packed f32x2 helpers
#define PACK2(d, s)      asm("mov.b64 %0, {%1, %1};" : "=l"(d) : "f"(s))
#define UNPK2(lo, hi, s) asm("mov.b64 {%0, %1}, %2;" : "=f"(lo), "=f"(hi) : "l"(s))
#define FMA2(d, a, b, c) asm("fma.rn.f32x2 %0, %1, %2, %3;" : "=l"(d) : "l"(a), "l"(b), "l"(c))
#define MUL2(d, a, b)    asm("mul.rn.f32x2 %0, %1, %2;" : "=l"(d) : "l"(a), "l"(b))
#define ADD2(d, a, b)    asm("add.rn.f32x2 %0, %1, %2;" : "=l"(d) : "l"(a), "l"(b))

// SMEM layout (floats):
//  Xs   [288*16]      = 4608   @0
//  vbuf [8*32*16]     = 4096   @4608
//  vcur [32*16]       = 512    @8704
//  invd [32]          = 32     @9216
//  mred [8*32]        = 256    @9248
//  nred [8*32]        = 256    @9504
#define SMEM_FLOATS 9760

// p_out has 4*32*16*8*8 = 131072 elements; a_out follows it.
#define AOUT_BASE 131072

#define LOADW(B, wa0, wb0, wa1, wb1, wa2, wb2, wa3, wb3)                       \
    {                                                                          \
        const ulonglong2* Wp_ =                                                \
            reinterpret_cast<const ulonglong2*>(Wt4_buf) + ((B) << 7) + lane;  \
        ulonglong2 t0 = Wp_[0], t1 = Wp_[32], t2 = Wp_[64], t3 = Wp_[96];      \
        wa0 = t0.x; wb0 = t0.y; wa1 = t1.x; wb1 = t1.y;                        \
        wa2 = t2.x; wb2 = t2.y; wa3 = t3.x; wb3 = t3.y;                        \
    }

// u[16] = X[B] (4x4) @ W (packed regs). 8 packed u64 results.
#define COMPUTE_U_P(B, wa0, wb0, wa1, wb1, wa2, wb2, wa3, wb3,                 \
                    ua0, ub0, ua1, ub1, ua2, ub2, ua3, ub3)                    \
    {                                                                          \
        const float4* Xp = Xv + ((B) << 2);                                    \
        float4 xr0 = Xp[0], xr1 = Xp[1], xr2 = Xp[2], xr3 = Xp[3];             \
        u64 xp0, xp1, xp2, xp3;                                                \
        PACK2(xp0, xr0.x); PACK2(xp1, xr0.y); PACK2(xp2, xr0.z); PACK2(xp3, xr0.w); \
        MUL2(ua0, xp0, wa0); MUL2(ub0, xp0, wb0);                              \
        FMA2(ua0, xp1, wa1, ua0); FMA2(ub0, xp1, wb1, ub0);                    \
        FMA2(ua0, xp2, wa2, ua0); FMA2(ub0, xp2, wb2, ub0);                    \
        FMA2(ua0, xp3, wa3, ua0); FMA2(ub0, xp3, wb3, ub0);                    \
        PACK2(xp0, xr1.x); PACK2(xp1, xr1.y); PACK2(xp2, xr1.z); PACK2(xp3, xr1.w); \
        MUL2(ua1, xp0, wa0); MUL2(ub1, xp0, wb0);                              \
        FMA2(ua1, xp1, wa1, ua1); FMA2(ub1, xp1, wb1, ub1);                    \
        FMA2(ua1, xp2, wa2, ua1); FMA2(ub1, xp2, wb2, ub1);                    \
        FMA2(ua1, xp3, wa3, ua1); FMA2(ub1, xp3, wb3, ub1);                    \
        PACK2(xp0, xr2.x); PACK2(xp1, xr2.y); PACK2(xp2, xr2.z); PACK2(xp3, xr2.w); \
        MUL2(ua2, xp0, wa0); MUL2(ub2, xp0, wb0);                              \
        FMA2(ua2, xp1, wa1, ua2); FMA2(ub2, xp1, wb1, ub2);                    \
        FMA2(ua2, xp2, wa2, ua2); FMA2(ub2, xp2, wb2, ub2);                    \
        FMA2(ua2, xp3, wa3, ua2); FMA2(ub2, xp3, wb3, ub2);                    \
        PACK2(xp0, xr3.x); PACK2(xp1, xr3.y); PACK2(xp2, xr3.z); PACK2(xp3, xr3.w); \
        MUL2(ua3, xp0, wa0); MUL2(ub3, xp0, wb0);                              \
        FMA2(ua3, xp1, wa1, ua3); FMA2(ub3, xp1, wb1, ub3);                    \
        FMA2(ua3, xp2, wa2, ua3); FMA2(ub3, xp2, wb2, ub3);                    \
        FMA2(ua3, xp3, wa3, ua3); FMA2(ub3, xp3, wb3, ub3);                    \
    }

// packed elementwise dot of 8 pairs -> scalar (lo+hi)
#define PDOT8(res, ua0, ub0, ua1, ub1, ua2, ub2, ua3, ub3,                     \
              va0, vb0, va1, vb1, va2, vb2, va3, vb3)                          \
    {                                                                          \
        u64 t_;                                                                \
        MUL2(t_, ua0, va0); FMA2(t_, ub0, vb0, t_);                            \
        FMA2(t_, ua1, va1, t_); FMA2(t_, ub1, vb1, t_);                        \
        FMA2(t_, ua2, va2, t_); FMA2(t_, ub2, vb2, t_);                        \
        FMA2(t_, ua3, va3, t_); FMA2(t_, ub3, vb3, t_);                        \
        float lo_, hi_;                                                        \
        UNPK2(lo_, hi_, t_);                                                   \
        res = lo_ + hi_;                                                       \
    }

__global__ __launch_bounds__(256, 2)
void convcaps_kernel(const float* __restrict__ x,
                     float* __restrict__ out) {
    extern __shared__ float smem[];
    float* Xs   = smem;
    float* vbuf = smem + 4608;
    float* vcur = smem + 8704;
    float* invd = smem + 9216;
    float* mred = smem + 9248;
    float* nred = smem + 9504;

    const int tid  = threadIdx.x;
    const int lane = tid & 31;     // = C
    const int wp   = tid >> 5;     // warp id, B ≡ wp (mod 8)
    const int pos  = blockIdx.x;   // b*64 + h*8 + w
    const int b    = pos >> 6;
    const int hw   = pos & 63;
    const int h    = hw >> 3;
    const int w    = hw & 7;

    // ---- gather patch poses X[B_=Bcap*9+ki*3+kj][ps] with zero padding ----
    for (int idx = tid; idx < 4608; idx += 256) {
        int B_ = idx >> 4, p = idx & 15;
        int Bcap = B_ / 9;
        int kk = B_ - Bcap * 9;
        int ki = kk / 3, kj = kk - ki * 3;
        int hh = 2 * h + ki - 1, ww = 2 * w + kj - 1;
        float val = 0.f;
        if ((unsigned)hh < 16u && (unsigned)ww < 16u)
            val = x[(((b * 32 + Bcap) * 16 + p) << 8) + (hh << 4) + ww];
        Xs[idx] = val;
    }
    __syncthreads();

    const float4* Xv     = reinterpret_cast<const float4*>(Xs);
    float4*       vbufv  = reinterpret_cast<float4*>(vbuf);
    float4*       vcurv  = reinterpret_cast<float4*>(vcur);
    ulonglong2*   vbufp  = reinterpret_cast<ulonglong2*>(vbuf);
    const ulonglong2* vcurp = reinterpret_cast<const ulonglong2*>(vcur);

    u64 aa0, ab0, aa1, ab1, aa2, ab2, aa3, ab3;

    // ================= PASS A: norms (for max-min) + uniform sum ==========
    {
        float mx = -3.4e38f, mn = 3.4e38f;
        u64 z = 0;
        aa0 = ab0 = aa1 = ab1 = aa2 = ab2 = aa3 = ab3 = z;
        u64 wa0, wb0, wa1, wb1, wa2, wb2, wa3, wb3;
        LOADW(wp, wa0, wb0, wa1, wb1, wa2, wb2, wa3, wb3)
        #pragma unroll 2
        for (int k = 0; k < 36; k++) {
            int B  = wp + (k << 3);
            int Bn = (k < 35) ? B + 8 : wp;
            u64 ua0, ub0, ua1, ub1, ua2, ub2, ua3, ub3;
            COMPUTE_U_P(B, wa0, wb0, wa1, wb1, wa2, wb2, wa3, wb3,
                           ua0, ub0, ua1, ub1, ua2, ub2, ua3, ub3)
            // reload same W registers for next iter (WAR, no extra regs)
            LOADW(Bn, wa0, wb0, wa1, wb1, wa2, wb2, wa3, wb3)
            float ss;
            PDOT8(ss, ua0, ub0, ua1, ub1, ua2, ub2, ua3, ub3,
                      ua0, ub0, ua1, ub1, ua2, ub2, ua3, ub3)
            float nrm = __fsqrt_rn(ss + EPSF);
            mx = fmaxf(mx, nrm);
            mn = fminf(mn, nrm);
            ADD2(aa0, aa0, ua0); ADD2(ab0, ab0, ub0);
            ADD2(aa1, aa1, ua1); ADD2(ab1, ab1, ub1);
            ADD2(aa2, aa2, ua2); ADD2(ab2, ab2, ub2);
            ADD2(aa3, aa3, ua3); ADD2(ab3, ab3, ub3);
        }
        mred[(wp << 5) + lane] = mx;
        nred[(wp << 5) + lane] = mn;
        int base = ((wp << 5) + lane) << 2;
        ulonglong2 s0; s0.x = aa0; s0.y = ab0; vbufp[base + 0] = s0;
        ulonglong2 s1; s1.x = aa1; s1.y = ab1; vbufp[base + 1] = s1;
        ulonglong2 s2; s2.x = aa2; s2.y = ab2; vbufp[base + 2] = s2;
        ulonglong2 s3; s3.x = aa3; s3.y = ab3; vbufp[base + 3] = s3;
    }
    __syncthreads();
    if (tid < 32) {
        float M = -3.4e38f, m = 3.4e38f;
        #pragma unroll
        for (int k = 0; k < 8; k++) {
            M = fmaxf(M, mred[(k << 5) + tid]);
            m = fminf(m, nred[(k << 5) + tid]);
        }
        invd[tid] = 1.f / (M - m);
    }
    __syncthreads();
    // reduce across warps + squash -> v0
    if (tid < 128) {
        int C = tid >> 2;
        float4 acc = vbufv[tid];
        #pragma unroll
        for (int k = 1; k < 8; k++) {
            float4 t = vbufv[(k << 7) + tid];
            acc.x += t.x; acc.y += t.y; acc.z += t.z; acc.w += t.w;
        }
        float f = invd[C] * (1.f / 32.f);
        acc.x *= f; acc.y *= f; acc.z *= f; acc.w *= f;
        float s = acc.x * acc.x + acc.y * acc.y + acc.z * acc.z + acc.w * acc.w;
        s += __shfl_xor_sync(0xffffffffu, s, 1);
        s += __shfl_xor_sync(0xffffffffu, s, 2);
        float nrm = __fsqrt_rn(s + EPSF);
        float g = 1.f / (1.f + nrm);
        acc.x *= g; acc.y *= g; acc.z *= g; acc.w *= g;
        vcurv[tid] = acc;
    }
    __syncthreads();

    const float invd_c = invd[lane];

    // v0 packed, kept in registers (pass C uses v0+v1 by linearity)
    u64 va0, vb0, va1, vb1, va2, vb2, va3, vb3;
    {
        ulonglong2 t0 = vcurp[(lane << 2) + 0];
        ulonglong2 t1 = vcurp[(lane << 2) + 1];
        ulonglong2 t2 = vcurp[(lane << 2) + 2];
        ulonglong2 t3 = vcurp[(lane << 2) + 3];
        va0 = t0.x; vb0 = t0.y; va1 = t1.x; vb1 = t1.y;
        va2 = t2.x; vb2 = t2.y; va3 = t3.x; vb3 = t3.y;
    }

// Routing pass body: collapsed-W pipelining + one-iteration deferred
// accumulation (acc += c_prev*u_prev issues under the shuffle chain).
#define ROUTING_PASS_LOOP                                                      \
    {                                                                          \
        u64 wa0, wb0, wa1, wb1, wa2, wb2, wa3, wb3;                            \
        LOADW(wp, wa0, wb0, wa1, wb1, wa2, wb2, wa3, wb3)                      \
        u64 up0 = 0, up1 = 0, up2 = 0, up3 = 0,                                \
            up4 = 0, up5 = 0, up6 = 0, up7 = 0;                                \
        u64 cP = 0;                                                            \
        _Pragma("unroll 2")                                                    \
        for (int k = 0; k < 36; k++) {                                         \
            int B  = wp + (k << 3);                                            \
            int Bn = (k < 35) ? B + 8 : wp;                                    \
            u64 ua0, ub0, ua1, ub1, ua2, ub2, ua3, ub3;                        \
            COMPUTE_U_P(B, wa0, wb0, wa1, wb1, wa2, wb2, wa3, wb3,             \
                           ua0, ub0, ua1, ub1, ua2, ub2, ua3, ub3)             \
            LOADW(Bn, wa0, wb0, wa1, wb1, wa2, wb2, wa3, wb3)                  \
            float dt;                                                          \
            PDOT8(dt, ua0, ub0, ua1, ub1, ua2, ub2, ua3, ub3,                  \
                      va0, vb0, va1, vb1, va2, vb2, va3, vb3)                  \
            float e = __expf(dt * invd_c);                                     \
            float s = e;                                                       \
            _Pragma("unroll")                                                  \
            for (int o = 16; o > 0; o >>= 1)                                   \
                s += __shfl_xor_sync(0xffffffffu, s, o);                       \
            /* deferred: previous iteration's accumulation (independent) */    \
            FMA2(aa0, cP, up0, aa0); FMA2(ab0, cP, up1, ab0);                  \
            FMA2(aa1, cP, up2, aa1); FMA2(ab1, cP, up3, ab1);                  \
            FMA2(aa2, cP, up4, aa2); FMA2(ab2, cP, up5, ab2);                  \
            FMA2(aa3, cP, up6, aa3); FMA2(ab3, cP, up7, ab3);                  \
            float c = __fdividef(e, s);                                        \
            PACK2(cP, c);                                                      \
            up0 = ua0; up1 = ub0; up2 = ua1; up3 = ub1;                        \
            up4 = ua2; up5 = ub2; up6 = ua3; up7 = ub3;                        \
        }                                                                      \
        /* tail flush */                                                       \
        FMA2(aa0, cP, up0, aa0); FMA2(ab0, cP, up1, ab0);                      \
        FMA2(aa1, cP, up2, aa1); FMA2(ab1, cP, up3, ab1);                      \
        FMA2(aa2, cP, up4, aa2); FMA2(ab2, cP, up5, ab2);                      \
        FMA2(aa3, cP, up6, aa3); FMA2(ab3, cP, up7, ab3);                      \
    }

    // ================= PASS B: r1 = u.v0, c1 = softmax_C, accum c1*u ======
    {
        u64 z = 0;
        aa0 = ab0 = aa1 = ab1 = aa2 = ab2 = aa3 = ab3 = z;
        ROUTING_PASS_LOOP
        int base = ((wp << 5) + lane) << 2;
        ulonglong2 s0; s0.x = aa0; s0.y = ab0; vbufp[base + 0] = s0;
        ulonglong2 s1; s1.x = aa1; s1.y = ab1; vbufp[base + 1] = s1;
        ulonglong2 s2; s2.x = aa2; s2.y = ab2; vbufp[base + 2] = s2;
        ulonglong2 s3; s3.x = aa3; s3.y = ab3; vbufp[base + 3] = s3;
    }
    __syncthreads();
    if (tid < 128) {
        int C = tid >> 2;
        float4 acc = vbufv[tid];
        #pragma unroll
        for (int k = 1; k < 8; k++) {
            float4 t = vbufv[(k << 7) + tid];
            acc.x += t.x; acc.y += t.y; acc.z += t.z; acc.w += t.w;
        }
        float f = invd[C];
        acc.x *= f; acc.y *= f; acc.z *= f; acc.w *= f;
        float s = acc.x * acc.x + acc.y * acc.y + acc.z * acc.z + acc.w * acc.w;
        s += __shfl_xor_sync(0xffffffffu, s, 1);
        s += __shfl_xor_sync(0xffffffffu, s, 2);
        float nrm = __fsqrt_rn(s + EPSF);
        float g = 1.f / (1.f + nrm);
        acc.x *= g; acc.y *= g; acc.z *= g; acc.w *= g;
        vcurv[tid] = acc;   // v1
    }
    __syncthreads();

    // vl = v0 + v1 (linearity: r2 = r1 + u.v1*invd = invd * u.(v0+v1))
    {
        ulonglong2 t0 = vcurp[(lane << 2) + 0];
        ulonglong2 t1 = vcurp[(lane << 2) + 1];
        ulonglong2 t2 = vcurp[(lane << 2) + 2];
        ulonglong2 t3 = vcurp[(lane << 2) + 3];
        ADD2(va0, va0, t0.x); ADD2(vb0, vb0, t0.y);
        ADD2(va1, va1, t1.x); ADD2(vb1, vb1, t1.y);
        ADD2(va2, va2, t2.x); ADD2(vb2, vb2, t2.y);
        ADD2(va3, va3, t3.x); ADD2(vb3, vb3, t3.y);
    }

    // ================= PASS C: r2 = invd*u.(v0+v1), c2, accum, output ======
    {
        u64 z = 0;
        aa0 = ab0 = aa1 = ab1 = aa2 = ab2 = aa3 = ab3 = z;
        ROUTING_PASS_LOOP
        int base = ((wp << 5) + lane) << 2;
        ulonglong2 s0; s0.x = aa0; s0.y = ab0; vbufp[base + 0] = s0;
        ulonglong2 s1; s1.x = aa1; s1.y = ab1; vbufp[base + 1] = s1;
        ulonglong2 s2; s2.x = aa2; s2.y = ab2; vbufp[base + 2] = s2;
        ulonglong2 s3; s3.x = aa3; s3.y = ab3; vbufp[base + 3] = s3;
    }
    __syncthreads();
    if (tid < 128) {
        int C = tid >> 2, q = tid & 3;
        float4 acc = vbufv[tid];
        #pragma unroll
        for (int k = 1; k < 8; k++) {
            float4 t = vbufv[(k << 7) + tid];
            acc.x += t.x; acc.y += t.y; acc.z += t.z; acc.w += t.w;
        }
        float f = invd[C];
        acc.x *= f; acc.y *= f; acc.z *= f; acc.w *= f;
        float s = acc.x * acc.x + acc.y * acc.y + acc.z * acc.z + acc.w * acc.w;
        s += __shfl_xor_sync(0xffffffffu, s, 1);
        s += __shfl_xor_sync(0xffffffffu, s, 2);
        float nrm = __fsqrt_rn(s + EPSF);
        float g = 1.f / (1.f + nrm);
        acc.x *= g; acc.y *= g; acc.z *= g; acc.w *= g;   // v2 (p_out)
        float s2 = acc.x * acc.x + acc.y * acc.y + acc.z * acc.z + acc.w * acc.w;
        s2 += __shfl_xor_sync(0xffffffffu, s2, 1);
        s2 += __shfl_xor_sync(0xffffffffu, s2, 2);
        float aout = __fsqrt_rn(s2 + EPSF);               // a_out = safe_norm(v2)
        int basep = (((b * 32 + C) * 16 + (q << 2)) << 6) + hw;
        out[basep]       = acc.x;
        out[basep + 64]  = acc.y;
        out[basep + 128] = acc.z;
        out[basep + 192] = acc.w;
        if (q == 0)
            out[AOUT_BASE + ((b * 32 + C) << 6) + hw] = aout;
    }
}

extern "C" void kernel_launch(void* const* d_in, const int* in_sizes, int n_in,
                              void* d_out, int out_size) {
    (void)out_size;
    // Resolve inputs BY SIZE — immune to metadata ordering.
    const float* x  = nullptr;
    const float* Wg = nullptr;
    for (int i = 0; i < n_in; i++) {
        if (in_sizes[i] == 524288)      x  = (const float*)d_in[i];
        else if (in_sizes[i] == 147456) Wg = (const float*)d_in[i];
    }
    float* out = (float*)d_out;

    transpose_W_kernel<<<(288 * 16 * 32 + 255) / 256, 256>>>(Wg);

    const size_t smem_bytes = SMEM_FLOATS * sizeof(float);
    cudaFuncSetAttribute(convcaps_kernel,
                         cudaFuncAttributeMaxDynamicSharedMemorySize,
                         (int)smem_bytes);
    convcaps_kernel<<<256, 256, smem_bytes>>>(x, out);
}

// round 14
// speedup vs baseline: 1.0882x; 1.0385x over previous
#include <cuda_runtime.h>
#include <math.h>

#define EPSF 1e-5f

// Re-laid-out weights: Wt4[B][g][C] (float4), g = jk/4.
__device__ float4 Wt4_buf[288 * 4 * 32];

__global__ void transpose_W_kernel(const float* __restrict__ Wg) {
    int idx = blockIdx.x * 256 + threadIdx.x;
    if (idx >= 288 * 16 * 32) return;
    int q = idx & 3;
    int C = (idx >> 2) & 31;
    int g = (idx >> 7) & 3;
    int B = idx >> 9;
    ((float*)Wt4_buf)[idx] = Wg[((B << 5) + C) * 16 + (g << 2) + q];
}

typedef unsigned long long u64;

// packed f32x2 helpers
#define PACK2(d, s)      asm("mov.b64 %0, {%1, %1};" : "=l"(d) : "f"(s))
#define UNPK2(lo, hi, s) asm("mov.b64 {%0, %1}, %2;" : "=f"(lo), "=f"(hi) : "l"(s))
#define FMA2(d, a, b, c) asm("fma.rn.f32x2 %0, %1, %2, %3;" : "=l"(d) : "l"(a), "l"(b), "l"(c))
#define MUL2(d, a, b)    asm("mul.rn.f32x2 %0, %1, %2;" : "=l"(d) : "l"(a), "l"(b))
#define ADD2(d, a, b)    asm("add.rn.f32x2 %0, %1, %2;" : "=l"(d) : "l"(a), "l"(b))

// SMEM layout (floats) — TWO positions per CTA:
//  Xs0  [288*16]      = 4608   @0
//  Xs1  [288*16]      = 4608   @4608
//  vbuf [2][8*32*16]  = 8192   @9216
//  vcur [2][32*16]    = 1024   @17408
//  invd [2][32]       = 64     @18432
//  mred [2][8*32]     = 512    @18496
//  nred [2][8*32]     = 512    @19008
#define SMEM_FLOATS 19520

// p_out has 4*32*16*8*8 = 131072 elements; a_out follows it.
#define AOUT_BASE 131072

#define LOADW(B, wa0, wb0, wa1, wb1, wa2, wb2, wa3, wb3)                       \
    {                                                                          \
        const ulonglong2* Wp_ =                                                \
            reinterpret_cast<const ulonglong2*>(Wt4_buf) + ((B) << 7) + lane;  \
        ulonglong2 t0 = Wp_[0], t1 = Wp_[32], t2 = Wp_[64], t3 = Wp_[96];      \
        wa0 = t0.x; wb0 = t0.y; wa1 = t1.x; wb1 = t1.y;                        \
        wa2 = t2.x; wb2 = t2.y; wa3 = t3.x; wb3 = t3.y;                        \
    }

// u[16] = X[B] (4x4) @ W (packed regs). XV = float4 view of a position's Xs.
#define COMPUTE_U_P(XV, B, ua0, ub0, ua1, ub1, ua2, ub2, ua3, ub3)             \
    {                                                                          \
        const float4* Xp = (XV) + ((B) << 2);                                  \
        float4 xr0 = Xp[0], xr1 = Xp[1], xr2 = Xp[2], xr3 = Xp[3];             \
        u64 xp0, xp1, xp2, xp3;                                                \
        PACK2(xp0, xr0.x); PACK2(xp1, xr0.y); PACK2(xp2, xr0.z); PACK2(xp3, xr0.w); \
        MUL2(ua0, xp0, wa0); MUL2(ub0, xp0, wb0);                              \
        FMA2(ua0, xp1, wa1, ua0); FMA2(ub0, xp1, wb1, ub0);                    \
        FMA2(ua0, xp2, wa2, ua0); FMA2(ub0, xp2, wb2, ub0);                    \
        FMA2(ua0, xp3, wa3, ua0); FMA2(ub0, xp3, wb3, ub0);                    \
        PACK2(xp0, xr1.x); PACK2(xp1, xr1.y); PACK2(xp2, xr1.z); PACK2(xp3, xr1.w); \
        MUL2(ua1, xp0, wa0); MUL2(ub1, xp0, wb0);                              \
        FMA2(ua1, xp1, wa1, ua1); FMA2(ub1, xp1, wb1, ub1);                    \
        FMA2(ua1, xp2, wa2, ua1); FMA2(ub1, xp2, wb2, ub1);                    \
        FMA2(ua1, xp3, wa3, ua1); FMA2(ub1, xp3, wb3, ub1);                    \
        PACK2(xp0, xr2.x); PACK2(xp1, xr2.y); PACK2(xp2, xr2.z); PACK2(xp3, xr2.w); \
        MUL2(ua2, xp0, wa0); MUL2(ub2, xp0, wb0);                              \
        FMA2(ua2, xp1, wa1, ua2); FMA2(ub2, xp1, wb1, ub2);                    \
        FMA2(ua2, xp2, wa2, ua2); FMA2(ub2, xp2, wb2, ub2);                    \
        FMA2(ua2, xp3, wa3, ua2); FMA2(ub2, xp3, wb3, ub2);                    \
        PACK2(xp0, xr3.x); PACK2(xp1, xr3.y); PACK2(xp2, xr3.z); PACK2(xp3, xr3.w); \
        MUL2(ua3, xp0, wa0); MUL2(ub3, xp0, wb0);                              \
        FMA2(ua3, xp1, wa1, ua3); FMA2(ub3, xp1, wb1, ub3);                    \
        FMA2(ua3, xp2, wa2, ua3); FMA2(ub3, xp2, wb2, ub3);                    \
        FMA2(ua3, xp3, wa3, ua3); FMA2(ub3, xp3, wb3, ub3);                    \
    }

// packed elementwise dot of 8 pairs -> scalar (lo+hi)
#define PDOT8(res, ua0, ub0, ua1, ub1, ua2, ub2, ua3, ub3,                     \
              va0, vb0, va1, vb1, va2, vb2, va3, vb3)                          \
    {                                                                          \
        u64 t_;                                                                \
        MUL2(t_, ua0, va0); FMA2(t_, ub0, vb0, t_);                            \
        FMA2(t_, ua1, va1, t_); FMA2(t_, ub1, vb1, t_);                        \
        FMA2(t_, ua2, va2, t_); FMA2(t_, ub2, vb2, t_);                        \
        FMA2(t_, ua3, va3, t_); FMA2(t_, ub3, vb3, t_);                        \
        float lo_, hi_;                                                        \
        UNPK2(lo_, hi_, t_);                                                   \
        res = lo_ + hi_;                                                       \
    }

__global__ __launch_bounds__(256, 1)
void convcaps_kernel(const float* __restrict__ x,
                     float* __restrict__ out) {
    extern __shared__ float smem[];
    float* Xs0  = smem;
    float* Xs1  = smem + 4608;
    float* vbuf = smem + 9216;
    float* vcur = smem + 17408;
    float* invd = smem + 18432;
    float* mred = smem + 18496;
    float* nred = smem + 19008;

    const int tid  = threadIdx.x;
    const int lane = tid & 31;       // = C
    const int wp   = tid >> 5;       // warp id, B ≡ wp (mod 8)
    const int pos0 = blockIdx.x * 2; // two positions per CTA

    // ---- gather patch poses for BOTH positions ----
    for (int idx = tid; idx < 9216; idx += 256) {
        int pp  = (idx >= 4608);
        int id2 = idx - (pp << 12) - (pp << 9);  // idx - pp*4608
        int pos = pos0 + pp;
        int b = pos >> 6, hw = pos & 63, h = hw >> 3, w = hw & 7;
        int B_ = id2 >> 4, p = id2 & 15;
        int Bcap = B_ / 9;
        int kk = B_ - Bcap * 9;
        int ki = kk / 3, kj = kk - ki * 3;
        int hh = 2 * h + ki - 1, ww = 2 * w + kj - 1;
        float val = 0.f;
        if ((unsigned)hh < 16u && (unsigned)ww < 16u)
            val = x[(((b * 32 + Bcap) * 16 + p) << 8) + (hh << 4) + ww];
        smem[idx] = val;
    }
    __syncthreads();

    const float4* Xv0 = reinterpret_cast<const float4*>(Xs0);
    const float4* Xv1 = reinterpret_cast<const float4*>(Xs1);
    float4*       vbufv = reinterpret_cast<float4*>(vbuf);
    float4*       vcurv = reinterpret_cast<float4*>(vcur);
    ulonglong2*   vbufp = reinterpret_cast<ulonglong2*>(vbuf);
    const ulonglong2* vcurp = reinterpret_cast<const ulonglong2*>(vcur);

    u64 p00, p01, p02, p03, p04, p05, p06, p07;   // acc pos0
    u64 p10, p11, p12, p13, p14, p15, p16, p17;   // acc pos1

    // ================= PASS A: norms (max-min) + uniform sums, both pos ===
    {
        float mx0 = -3.4e38f, mn0 = 3.4e38f, mx1 = -3.4e38f, mn1 = 3.4e38f;
        p00 = p01 = p02 = p03 = p04 = p05 = p06 = p07 = 0;
        p10 = p11 = p12 = p13 = p14 = p15 = p16 = p17 = 0;
        u64 wa0, wb0, wa1, wb1, wa2, wb2, wa3, wb3;
        LOADW(wp, wa0, wb0, wa1, wb1, wa2, wb2, wa3, wb3)
        for (int k = 0; k < 36; k++) {
            int B  = wp + (k << 3);
            int Bn = (k < 35) ? B + 8 : wp;
            u64 ua0, ub0, ua1, ub1, ua2, ub2, ua3, ub3;
            u64 za0, zb0, za1, zb1, za2, zb2, za3, zb3;
            COMPUTE_U_P(Xv0, B, ua0, ub0, ua1, ub1, ua2, ub2, ua3, ub3)
            COMPUTE_U_P(Xv1, B, za0, zb0, za1, zb1, za2, zb2, za3, zb3)
            LOADW(Bn, wa0, wb0, wa1, wb1, wa2, wb2, wa3, wb3)
            float s0, s1;
            PDOT8(s0, ua0, ub0, ua1, ub1, ua2, ub2, ua3, ub3,
                      ua0, ub0, ua1, ub1, ua2, ub2, ua3, ub3)
            PDOT8(s1, za0, zb0, za1, zb1, za2, zb2, za3, zb3,
                      za0, zb0, za1, zb1, za2, zb2, za3, zb3)
            float n0 = __fsqrt_rn(s0 + EPSF);
            float n1 = __fsqrt_rn(s1 + EPSF);
            mx0 = fmaxf(mx0, n0); mn0 = fminf(mn0, n0);
            mx1 = fmaxf(mx1, n1); mn1 = fminf(mn1, n1);
            ADD2(p00, p00, ua0); ADD2(p01, p01, ub0);
            ADD2(p02, p02, ua1); ADD2(p03, p03, ub1);
            ADD2(p04, p04, ua2); ADD2(p05, p05, ub2);
            ADD2(p06, p06, ua3); ADD2(p07, p07, ub3);
            ADD2(p10, p10, za0); ADD2(p11, p11, zb0);
            ADD2(p12, p12, za1); ADD2(p13, p13, zb1);
            ADD2(p14, p14, za2); ADD2(p15, p15, zb2);
            ADD2(p16, p16, za3); ADD2(p17, p17, zb3);
        }
        mred[(wp << 5) + lane]       = mx0;
        nred[(wp << 5) + lane]       = mn0;
        mred[256 + (wp << 5) + lane] = mx1;
        nred[256 + (wp << 5) + lane] = mn1;
        int base = ((wp << 5) + lane) << 2;
        ulonglong2 t;
        t.x = p00; t.y = p01; vbufp[base + 0] = t;
        t.x = p02; t.y = p03; vbufp[base + 1] = t;
        t.x = p04; t.y = p05; vbufp[base + 2] = t;
        t.x = p06; t.y = p07; vbufp[base + 3] = t;
        t.x = p10; t.y = p11; vbufp[1024 + base + 0] = t;
        t.x = p12; t.y = p13; vbufp[1024 + base + 1] = t;
        t.x = p14; t.y = p15; vbufp[1024 + base + 2] = t;
        t.x = p16; t.y = p17; vbufp[1024 + base + 3] = t;
    }
    __syncthreads();
    if (tid < 64) {
        int pp = tid >> 5, c = tid & 31;
        float M = -3.4e38f, m = 3.4e38f;
        #pragma unroll
        for (int k = 0; k < 8; k++) {
            M = fmaxf(M, mred[pp * 256 + (k << 5) + c]);
            m = fminf(m, nred[pp * 256 + (k << 5) + c]);
        }
        invd[(pp << 5) + c] = 1.f / (M - m);
    }
    __syncthreads();
    // reduce across warps + squash -> v0 for both positions (all 256 thr)
    {
        int t = tid & 127, pp = tid >> 7;
        int C = t >> 2;
        int off = pp << 10;
        float4 acc = vbufv[off + t];
        #pragma unroll
        for (int k = 1; k < 8; k++) {
            float4 u = vbufv[off + (k << 7) + t];
            acc.x += u.x; acc.y += u.y; acc.z += u.z; acc.w += u.w;
        }
        float f = invd[(pp << 5) + C] * (1.f / 32.f);
        acc.x *= f; acc.y *= f; acc.z *= f; acc.w *= f;
        float s = acc.x * acc.x + acc.y * acc.y + acc.z * acc.z + acc.w * acc.w;
        s += __shfl_xor_sync(0xffffffffu, s, 1);
        s += __shfl_xor_sync(0xffffffffu, s, 2);
        float nrm = __fsqrt_rn(s + EPSF);
        float g = 1.f / (1.f + nrm);
        acc.x *= g; acc.y *= g; acc.z *= g; acc.w *= g;
        vcurv[(pp << 7) + t] = acc;
    }
    __syncthreads();

    const float invd0 = invd[lane];
    const float invd1 = invd[32 + lane];

    // v0 packed per position, kept in registers
    u64 A0, A1, A2, A3, A4, A5, A6, A7;   // v (pos0)
    u64 B0, B1, B2, B3, B4, B5, B6, B7;   // v (pos1)
    {
        ulonglong2 t0 = vcurp[(lane << 2) + 0];
        ulonglong2 t1 = vcurp[(lane << 2) + 1];
        ulonglong2 t2 = vcurp[(lane << 2) + 2];
        ulonglong2 t3 = vcurp[(lane << 2) + 3];
        A0 = t0.x; A1 = t0.y; A2 = t1.x; A3 = t1.y;
        A4 = t2.x; A5 = t2.y; A6 = t3.x; A7 = t3.y;
        t0 = vcurp[128 + (lane << 2) + 0];
        t1 = vcurp[128 + (lane << 2) + 1];
        t2 = vcurp[128 + (lane << 2) + 2];
        t3 = vcurp[128 + (lane << 2) + 3];
        B0 = t0.x; B1 = t0.y; B2 = t1.x; B3 = t1.y;
        B4 = t2.x; B5 = t2.y; B6 = t3.x; B7 = t3.y;
    }

// Routing pass: one W load feeds both positions; twin shuffle chains.
#define ROUTING_PASS_LOOP                                                      \
    {                                                                          \
        u64 wa0, wb0, wa1, wb1, wa2, wb2, wa3, wb3;                            \
        LOADW(wp, wa0, wb0, wa1, wb1, wa2, wb2, wa3, wb3)                      \
        for (int k = 0; k < 36; k++) {                                         \
            int B  = wp + (k << 3);                                            \
            int Bn = (k < 35) ? B + 8 : wp;                                    \
            u64 ua0, ub0, ua1, ub1, ua2, ub2, ua3, ub3;                        \
            u64 za0, zb0, za1, zb1, za2, zb2, za3, zb3;                        \
            COMPUTE_U_P(Xv0, B, ua0, ub0, ua1, ub1, ua2, ub2, ua3, ub3)        \
            COMPUTE_U_P(Xv1, B, za0, zb0, za1, zb1, za2, zb2, za3, zb3)        \
            LOADW(Bn, wa0, wb0, wa1, wb1, wa2, wb2, wa3, wb3)                  \
            float d0, d1;                                                      \
            PDOT8(d0, ua0, ub0, ua1, ub1, ua2, ub2, ua3, ub3,                  \
                      A0, A1, A2, A3, A4, A5, A6, A7)                          \
            PDOT8(d1, za0, zb0, za1, zb1, za2, zb2, za3, zb3,                  \
                      B0, B1, B2, B3, B4, B5, B6, B7)                          \
            float e0 = __expf(d0 * invd0);                                     \
            float e1 = __expf(d1 * invd1);                                     \
            float s0 = e0, s1 = e1;                                            \
            _Pragma("unroll")                                                  \
            for (int o = 16; o > 0; o >>= 1) {                                 \
                s0 += __shfl_xor_sync(0xffffffffu, s0, o);                     \
                s1 += __shfl_xor_sync(0xffffffffu, s1, o);                     \
            }                                                                  \
            float c0 = __fdividef(e0, s0);                                     \
            float c1 = __fdividef(e1, s1);                                     \
            u64 c0P, c1P;                                                      \
            PACK2(c0P, c0); PACK2(c1P, c1);                                    \
            FMA2(p00, c0P, ua0, p00); FMA2(p01, c0P, ub0, p01);                \
            FMA2(p02, c0P, ua1, p02); FMA2(p03, c0P, ub1, p03);                \
            FMA2(p04, c0P, ua2, p04); FMA2(p05, c0P, ub2, p05);                \
            FMA2(p06, c0P, ua3, p06); FMA2(p07, c0P, ub3, p07);                \
            FMA2(p10, c1P, za0, p10); FMA2(p11, c1P, zb0, p11);                \
            FMA2(p12, c1P, za1, p12); FMA2(p13, c1P, zb1, p13);                \
            FMA2(p14, c1P, za2, p14); FMA2(p15, c1P, zb2, p15);                \
            FMA2(p16, c1P, za3, p16); FMA2(p17, c1P, zb3, p17);                \
        }                                                                      \
    }

#define STORE_ACC                                                              \
    {                                                                          \
        int base = ((wp << 5) + lane) << 2;                                    \
        ulonglong2 t;                                                          \
        t.x = p00; t.y = p01; vbufp[base + 0] = t;                             \
        t.x = p02; t.y = p03; vbufp[base + 1] = t;                             \
        t.x = p04; t.y = p05; vbufp[base + 2] = t;                             \
        t.x = p06; t.y = p07; vbufp[base + 3] = t;                             \
        t.x = p10; t.y = p11; vbufp[1024 + base + 0] = t;                      \
        t.x = p12; t.y = p13; vbufp[1024 + base + 1] = t;                      \
        t.x = p14; t.y = p15; vbufp[1024 + base + 2] = t;                      \
        t.x = p16; t.y = p17; vbufp[1024 + base + 3] = t;                      \
    }

    // ================= PASS B: r1, c1, accumulate ========================
    {
        p00 = p01 = p02 = p03 = p04 = p05 = p06 = p07 = 0;
        p10 = p11 = p12 = p13 = p14 = p15 = p16 = p17 = 0;
        ROUTING_PASS_LOOP
        STORE_ACC
    }
    __syncthreads();
    {
        int t = tid & 127, pp = tid >> 7;
        int C = t >> 2;
        int off = pp << 10;
        float4 acc = vbufv[off + t];
        #pragma unroll
        for (int k = 1; k < 8; k++) {
            float4 u = vbufv[off + (k << 7) + t];
            acc.x += u.x; acc.y += u.y; acc.z += u.z; acc.w += u.w;
        }
        float f = invd[(pp << 5) + C];
        acc.x *= f; acc.y *= f; acc.z *= f; acc.w *= f;
        float s = acc.x * acc.x + acc.y * acc.y + acc.z * acc.z + acc.w * acc.w;
        s += __shfl_xor_sync(0xffffffffu, s, 1);
        s += __shfl_xor_sync(0xffffffffu, s, 2);
        float nrm = __fsqrt_rn(s + EPSF);
        float g = 1.f / (1.f + nrm);
        acc.x *= g; acc.y *= g; acc.z *= g; acc.w *= g;
        vcurv[(pp << 7) + t] = acc;   // v1
    }
    __syncthreads();

    // v <- v0 + v1 per position (linearity of r)
    {
        ulonglong2 t0 = vcurp[(lane << 2) + 0];
        ulonglong2 t1 = vcurp[(lane << 2) + 1];
        ulonglong2 t2 = vcurp[(lane << 2) + 2];
        ulonglong2 t3 = vcurp[(lane << 2) + 3];
        ADD2(A0, A0, t0.x); ADD2(A1, A1, t0.y);
        ADD2(A2, A2, t1.x); ADD2(A3, A3, t1.y);
        ADD2(A4, A4, t2.x); ADD2(A5, A5, t2.y);
        ADD2(A6, A6, t3.x); ADD2(A7, A7, t3.y);
        t0 = vcurp[128 + (lane << 2) + 0];
        t1 = vcurp[128 + (lane << 2) + 1];
        t2 = vcurp[128 + (lane << 2) + 2];
        t3 = vcurp[128 + (lane << 2) + 3];
        ADD2(B0, B0, t0.x); ADD2(B1, B1, t0.y);
        ADD2(B2, B2, t1.x); ADD2(B3, B3, t1.y);
        ADD2(B4, B4, t2.x); ADD2(B5, B5, t2.y);
        ADD2(B6, B6, t3.x); ADD2(B7, B7, t3.y);
    }

    // ================= PASS C: r2, c2, accumulate, output ================
    {
        p00 = p01 = p02 = p03 = p04 = p05 = p06 = p07 = 0;
        p10 = p11 = p12 = p13 = p14 = p15 = p16 = p17 = 0;
        ROUTING_PASS_LOOP
        STORE_ACC
    }
    __syncthreads();
    {
        int t = tid & 127, pp = tid >> 7;
        int C = t >> 2, q = t & 3;
        int off = pp << 10;
        float4 acc = vbufv[off + t];
        #pragma unroll
        for (int k = 1; k < 8; k++) {
            float4 u = vbufv[off + (k << 7) + t];
            acc.x += u.x; acc.y += u.y; acc.z += u.z; acc.w += u.w;
        }
        float f = invd[(pp << 5) + C];
        acc.x *= f; acc.y *= f; acc.z *= f; acc.w *= f;
        float s = acc.x * acc.x + acc.y * acc.y + acc.z * acc.z + acc.w * acc.w;
        s += __shfl_xor_sync(0xffffffffu, s, 1);
        s += __shfl_xor_sync(0xffffffffu, s, 2);
        float nrm = __fsqrt_rn(s + EPSF);
        float g = 1.f / (1.f + nrm);
        acc.x *= g; acc.y *= g; acc.z *= g; acc.w *= g;   // v2 (p_out)
        float s2 = acc.x * acc.x + acc.y * acc.y + acc.z * acc.z + acc.w * acc.w;
        s2 += __shfl_xor_sync(0xffffffffu, s2, 1);
        s2 += __shfl_xor_sync(0xffffffffu, s2, 2);
        float aout = __fsqrt_rn(s2 + EPSF);               // a_out = safe_norm(v2)
        int pos = pos0 + pp;
        int b = pos >> 6, hw = pos & 63;
        int basep = (((b * 32 + C) * 16 + (q << 2)) << 6) + hw;
        out[basep]       = acc.x;
        out[basep + 64]  = acc.y;
        out[basep + 128] = acc.z;
        out[basep + 192] = acc.w;
        if (q == 0)
            out[AOUT_BASE + ((b * 32 + C) << 6) + hw] = aout;
    }
}

extern "C" void kernel_launch(void* const* d_in, const int* in_sizes, int n_in,
                              void* d_out, int out_size) {
    (void)out_size;
    // Resolve inputs BY SIZE — immune to metadata ordering.
    const float* x  = nullptr;
    const float* Wg = nullptr;
    for (int i = 0; i < n_in; i++) {
        if (in_sizes[i] == 524288)      x  = (const float*)d_in[i];
        else if (in_sizes[i] == 147456) Wg = (const float*)d_in[i];
    }
    float* out = (float*)d_out;

    transpose_W_kernel<<<(288 * 16 * 32 + 255) / 256, 256>>>(Wg);

    const size_t smem_bytes = SMEM_FLOATS * sizeof(float);
    cudaFuncSetAttribute(convcaps_kernel,
                         cudaFuncAttributeMaxDynamicSharedMemorySize,
                         (int)smem_bytes);
    convcaps_kernel<<<128, 256, smem_bytes>>>(x, out);
}

// round 15
// speedup vs baseline: 1.2097x; 1.1117x over previous
#include <cuda_runtime.h>
#include <math.h>

#define EPSF 1e-5f
#define NW 12            // warps per CTA
#define NITER 24         // 288 / NW

// Re-laid-out weights: Wt4[B][g][C] (float4), g = jk/4.
__device__ float4 Wt4_buf[288 * 4 * 32];

__global__ void transpose_W_kernel(const float* __restrict__ Wg) {
    int idx = blockIdx.x * 256 + threadIdx.x;
    if (idx >= 288 * 16 * 32) return;
    int q = idx & 3;
    int C = (idx >> 2) & 31;
    int g = (idx >> 7) & 3;
    int B = idx >> 9;
    ((float*)Wt4_buf)[idx] = Wg[((B << 5) + C) * 16 + (g << 2) + q];
}

typedef unsigned long long u64;

// packed f32x2 helpers
#define PACK2(d, s)      asm("mov.b64 %0, {%1, %1};" : "=l"(d) : "f"(s))
#define UNPK2(lo, hi, s) asm("mov.b64 {%0, %1}, %2;" : "=f"(lo), "=f"(hi) : "l"(s))
#define FMA2(d, a, b, c) asm("fma.rn.f32x2 %0, %1, %2, %3;" : "=l"(d) : "l"(a), "l"(b), "l"(c))
#define MUL2(d, a, b)    asm("mul.rn.f32x2 %0, %1, %2;" : "=l"(d) : "l"(a), "l"(b))
#define ADD2(d, a, b)    asm("add.rn.f32x2 %0, %1, %2;" : "=l"(d) : "l"(a), "l"(b))

// SMEM layout (floats) — TWO positions per CTA, 12 warps:
//  Xs0  [288*16]        = 4608   @0
//  Xs1  [288*16]        = 4608   @4608
//  vbuf [2][12*32*16]   = 12288  @9216
//  vcur [2][32*16]      = 1024   @21504
//  invd [2][32]         = 64     @22528
//  mred [2][12*32]      = 768    @22592
//  nred [2][12*32]      = 768    @23360
#define SMEM_FLOATS 24128

// p_out has 4*32*16*8*8 = 131072 elements; a_out follows it.
#define AOUT_BASE 131072

#define LOADW(B, wa0, wb0, wa1, wb1, wa2, wb2, wa3, wb3)                       \
    {                                                                          \
        const ulonglong2* Wp_ =                                                \
            reinterpret_cast<const ulonglong2*>(Wt4_buf) + ((B) << 7) + lane;  \
        ulonglong2 t0 = Wp_[0], t1 = Wp_[32], t2 = Wp_[64], t3 = Wp_[96];      \
        wa0 = t0.x; wb0 = t0.y; wa1 = t1.x; wb1 = t1.y;                        \
        wa2 = t2.x; wb2 = t2.y; wa3 = t3.x; wb3 = t3.y;                        \
    }

// u[16] = X[B] (4x4) @ W (packed regs). XV = float4 view of a position's Xs.
#define COMPUTE_U_P(XV, B, ua0, ub0, ua1, ub1, ua2, ub2, ua3, ub3)             \
    {                                                                          \
        const float4* Xp = (XV) + ((B) << 2);                                  \
        float4 xr0 = Xp[0], xr1 = Xp[1], xr2 = Xp[2], xr3 = Xp[3];             \
        u64 xp0, xp1, xp2, xp3;                                                \
        PACK2(xp0, xr0.x); PACK2(xp1, xr0.y); PACK2(xp2, xr0.z); PACK2(xp3, xr0.w); \
        MUL2(ua0, xp0, wa0); MUL2(ub0, xp0, wb0);                              \
        FMA2(ua0, xp1, wa1, ua0); FMA2(ub0, xp1, wb1, ub0);                    \
        FMA2(ua0, xp2, wa2, ua0); FMA2(ub0, xp2, wb2, ub0);                    \
        FMA2(ua0, xp3, wa3, ua0); FMA2(ub0, xp3, wb3, ub0);                    \
        PACK2(xp0, xr1.x); PACK2(xp1, xr1.y); PACK2(xp2, xr1.z); PACK2(xp3, xr1.w); \
        MUL2(ua1, xp0, wa0); MUL2(ub1, xp0, wb0);                              \
        FMA2(ua1, xp1, wa1, ua1); FMA2(ub1, xp1, wb1, ub1);                    \
        FMA2(ua1, xp2, wa2, ua1); FMA2(ub1, xp2, wb2, ub1);                    \
        FMA2(ua1, xp3, wa3, ua1); FMA2(ub1, xp3, wb3, ub1);                    \
        PACK2(xp0, xr2.x); PACK2(xp1, xr2.y); PACK2(xp2, xr2.z); PACK2(xp3, xr2.w); \
        MUL2(ua2, xp0, wa0); MUL2(ub2, xp0, wb0);                              \
        FMA2(ua2, xp1, wa1, ua2); FMA2(ub2, xp1, wb1, ub2);                    \
        FMA2(ua2, xp2, wa2, ua2); FMA2(ub2, xp2, wb2, ub2);                    \
        FMA2(ua2, xp3, wa3, ua2); FMA2(ub2, xp3, wb3, ub2);                    \
        PACK2(xp0, xr3.x); PACK2(xp1, xr3.y); PACK2(xp2, xr3.z); PACK2(xp3, xr3.w); \
        MUL2(ua3, xp0, wa0); MUL2(ub3, xp0, wb0);                              \
        FMA2(ua3, xp1, wa1, ua3); FMA2(ub3, xp1, wb1, ub3);                    \
        FMA2(ua3, xp2, wa2, ua3); FMA2(ub3, xp2, wb2, ub3);                    \
        FMA2(ua3, xp3, wa3, ua3); FMA2(ub3, xp3, wb3, ub3);                    \
    }

// packed elementwise dot of 8 pairs -> scalar (lo+hi)
#define PDOT8(res, ua0, ub0, ua1, ub1, ua2, ub2, ua3, ub3,                     \
              va0, vb0, va1, vb1, va2, vb2, va3, vb3)                          \
    {                                                                          \
        u64 t_;                                                                \
        MUL2(t_, ua0, va0); FMA2(t_, ub0, vb0, t_);                            \
        FMA2(t_, ua1, va1, t_); FMA2(t_, ub1, vb1, t_);                        \
        FMA2(t_, ua2, va2, t_); FMA2(t_, ub2, vb2, t_);                        \
        FMA2(t_, ua3, va3, t_); FMA2(t_, ub3, vb3, t_);                        \
        float lo_, hi_;                                                        \
        UNPK2(lo_, hi_, t_);                                                   \
        res = lo_ + hi_;                                                       \
    }

__global__ __launch_bounds__(384, 1)
void convcaps_kernel(const float* __restrict__ x,
                     float* __restrict__ out) {
    extern __shared__ float smem[];
    float* Xs0  = smem;
    float* Xs1  = smem + 4608;
    float* vbuf = smem + 9216;
    float* vcur = smem + 21504;
    float* invd = smem + 22528;
    float* mred = smem + 22592;
    float* nred = smem + 23360;

    const int tid  = threadIdx.x;
    const int lane = tid & 31;       // = C
    const int wp   = tid >> 5;       // warp id 0..11, B ≡ wp (mod 12)
    const int pos0 = blockIdx.x * 2; // two positions per CTA

    // ---- gather patch poses for BOTH positions ----
    for (int idx = tid; idx < 9216; idx += 384) {
        int pp  = (idx >= 4608);
        int id2 = idx - pp * 4608;
        int pos = pos0 + pp;
        int b = pos >> 6, hw = pos & 63, h = hw >> 3, w = hw & 7;
        int B_ = id2 >> 4, p = id2 & 15;
        int Bcap = B_ / 9;
        int kk = B_ - Bcap * 9;
        int ki = kk / 3, kj = kk - ki * 3;
        int hh = 2 * h + ki - 1, ww = 2 * w + kj - 1;
        float val = 0.f;
        if ((unsigned)hh < 16u && (unsigned)ww < 16u)
            val = x[(((b * 32 + Bcap) * 16 + p) << 8) + (hh << 4) + ww];
        smem[idx] = val;
    }
    __syncthreads();

    const float4* Xv0 = reinterpret_cast<const float4*>(Xs0);
    const float4* Xv1 = reinterpret_cast<const float4*>(Xs1);
    float4*       vbufv = reinterpret_cast<float4*>(vbuf);
    float4*       vcurv = reinterpret_cast<float4*>(vcur);
    ulonglong2*   vbufp = reinterpret_cast<ulonglong2*>(vbuf);
    const ulonglong2* vcurp = reinterpret_cast<const ulonglong2*>(vcur);

    u64 p00, p01, p02, p03, p04, p05, p06, p07;   // acc pos0
    u64 p10, p11, p12, p13, p14, p15, p16, p17;   // acc pos1

    // per-pos vbuf stride: 12*32*16 floats = 1536 float4 = 1536 ulonglong2
    const int VB1 = 1536;

    // ================= PASS A: norms (max-min) + uniform sums, both pos ===
    {
        float mx0 = -3.4e38f, mn0 = 3.4e38f, mx1 = -3.4e38f, mn1 = 3.4e38f;
        p00 = p01 = p02 = p03 = p04 = p05 = p06 = p07 = 0;
        p10 = p11 = p12 = p13 = p14 = p15 = p16 = p17 = 0;
        u64 wa0, wb0, wa1, wb1, wa2, wb2, wa3, wb3;
        LOADW(wp, wa0, wb0, wa1, wb1, wa2, wb2, wa3, wb3)
        for (int k = 0; k < NITER; k++) {
            int B  = wp + k * NW;
            int Bn = (k < NITER - 1) ? B + NW : wp;
            u64 ua0, ub0, ua1, ub1, ua2, ub2, ua3, ub3;
            u64 za0, zb0, za1, zb1, za2, zb2, za3, zb3;
            COMPUTE_U_P(Xv0, B, ua0, ub0, ua1, ub1, ua2, ub2, ua3, ub3)
            COMPUTE_U_P(Xv1, B, za0, zb0, za1, zb1, za2, zb2, za3, zb3)
            LOADW(Bn, wa0, wb0, wa1, wb1, wa2, wb2, wa3, wb3)
            float s0, s1;
            PDOT8(s0, ua0, ub0, ua1, ub1, ua2, ub2, ua3, ub3,
                      ua0, ub0, ua1, ub1, ua2, ub2, ua3, ub3)
            PDOT8(s1, za0, zb0, za1, zb1, za2, zb2, za3, zb3,
                      za0, zb0, za1, zb1, za2, zb2, za3, zb3)
            float n0 = __fsqrt_rn(s0 + EPSF);
            float n1 = __fsqrt_rn(s1 + EPSF);
            mx0 = fmaxf(mx0, n0); mn0 = fminf(mn0, n0);
            mx1 = fmaxf(mx1, n1); mn1 = fminf(mn1, n1);
            ADD2(p00, p00, ua0); ADD2(p01, p01, ub0);
            ADD2(p02, p02, ua1); ADD2(p03, p03, ub1);
            ADD2(p04, p04, ua2); ADD2(p05, p05, ub2);
            ADD2(p06, p06, ua3); ADD2(p07, p07, ub3);
            ADD2(p10, p10, za0); ADD2(p11, p11, zb0);
            ADD2(p12, p12, za1); ADD2(p13, p13, zb1);
            ADD2(p14, p14, za2); ADD2(p15, p15, zb2);
            ADD2(p16, p16, za3); ADD2(p17, p17, zb3);
        }
        mred[(wp << 5) + lane]       = mx0;
        nred[(wp << 5) + lane]       = mn0;
        mred[384 + (wp << 5) + lane] = mx1;
        nred[384 + (wp << 5) + lane] = mn1;
        int base = ((wp << 5) + lane) << 2;
        ulonglong2 t;
        t.x = p00; t.y = p01; vbufp[base + 0] = t;
        t.x = p02; t.y = p03; vbufp[base + 1] = t;
        t.x = p04; t.y = p05; vbufp[base + 2] = t;
        t.x = p06; t.y = p07; vbufp[base + 3] = t;
        t.x = p10; t.y = p11; vbufp[VB1 + base + 0] = t;
        t.x = p12; t.y = p13; vbufp[VB1 + base + 1] = t;
        t.x = p14; t.y = p15; vbufp[VB1 + base + 2] = t;
        t.x = p16; t.y = p17; vbufp[VB1 + base + 3] = t;
    }
    __syncthreads();
    if (tid < 64) {
        int pp = tid >> 5, c = tid & 31;
        float M = -3.4e38f, m = 3.4e38f;
        #pragma unroll
        for (int k = 0; k < NW; k++) {
            M = fmaxf(M, mred[pp * 384 + (k << 5) + c]);
            m = fminf(m, nred[pp * 384 + (k << 5) + c]);
        }
        invd[(pp << 5) + c] = 1.f / (M - m);
    }
    __syncthreads();
    // reduce across warps + squash -> v0 for both positions (256 threads)
    if (tid < 256) {
        int t = tid & 127, pp = tid >> 7;
        int C = t >> 2;
        int off = pp * VB1;
        float4 acc = vbufv[off + t];
        #pragma unroll
        for (int k = 1; k < NW; k++) {
            float4 u = vbufv[off + (k << 7) + t];
            acc.x += u.x; acc.y += u.y; acc.z += u.z; acc.w += u.w;
        }
        float f = invd[(pp << 5) + C] * (1.f / 32.f);
        acc.x *= f; acc.y *= f; acc.z *= f; acc.w *= f;
        float s = acc.x * acc.x + acc.y * acc.y + acc.z * acc.z + acc.w * acc.w;
        s += __shfl_xor_sync(0xffffffffu, s, 1);
        s += __shfl_xor_sync(0xffffffffu, s, 2);
        float nrm = __fsqrt_rn(s + EPSF);
        float g = 1.f / (1.f + nrm);
        acc.x *= g; acc.y *= g; acc.z *= g; acc.w *= g;
        vcurv[(pp << 7) + t] = acc;
    }
    __syncthreads();

    const float invd0 = invd[lane];
    const float invd1 = invd[32 + lane];

    // v0 packed per position, kept in registers
    u64 A0, A1, A2, A3, A4, A5, A6, A7;   // v (pos0)
    u64 B0, B1, B2, B3, B4, B5, B6, B7;   // v (pos1)
    {
        ulonglong2 t0 = vcurp[(lane << 2) + 0];
        ulonglong2 t1 = vcurp[(lane << 2) + 1];
        ulonglong2 t2 = vcurp[(lane << 2) + 2];
        ulonglong2 t3 = vcurp[(lane << 2) + 3];
        A0 = t0.x; A1 = t0.y; A2 = t1.x; A3 = t1.y;
        A4 = t2.x; A5 = t2.y; A6 = t3.x; A7 = t3.y;
        t0 = vcurp[128 + (lane << 2) + 0];
        t1 = vcurp[128 + (lane << 2) + 1];
        t2 = vcurp[128 + (lane << 2) + 2];
        t3 = vcurp[128 + (lane << 2) + 3];
        B0 = t0.x; B1 = t0.y; B2 = t1.x; B3 = t1.y;
        B4 = t2.x; B5 = t2.y; B6 = t3.x; B7 = t3.y;
    }

// Routing pass: one W load feeds both positions; twin shuffle chains.
#define ROUTING_PASS_LOOP                                                      \
    {                                                                          \
        u64 wa0, wb0, wa1, wb1, wa2, wb2, wa3, wb3;                            \
        LOADW(wp, wa0, wb0, wa1, wb1, wa2, wb2, wa3, wb3)                      \
        for (int k = 0; k < NITER; k++) {                                      \
            int B  = wp + k * NW;                                              \
            int Bn = (k < NITER - 1) ? B + NW : wp;                            \
            u64 ua0, ub0, ua1, ub1, ua2, ub2, ua3, ub3;                        \
            u64 za0, zb0, za1, zb1, za2, zb2, za3, zb3;                        \
            COMPUTE_U_P(Xv0, B, ua0, ub0, ua1, ub1, ua2, ub2, ua3, ub3)        \
            COMPUTE_U_P(Xv1, B, za0, zb0, za1, zb1, za2, zb2, za3, zb3)        \
            LOADW(Bn, wa0, wb0, wa1, wb1, wa2, wb2, wa3, wb3)                  \
            float d0, d1;                                                      \
            PDOT8(d0, ua0, ub0, ua1, ub1, ua2, ub2, ua3, ub3,                  \
                      A0, A1, A2, A3, A4, A5, A6, A7)                          \
            PDOT8(d1, za0, zb0, za1, zb1, za2, zb2, za3, zb3,                  \
                      B0, B1, B2, B3, B4, B5, B6, B7)                          \
            float e0 = __expf(d0 * invd0);                                     \
            float e1 = __expf(d1 * invd1);                                     \
            float s0 = e0, s1 = e1;                                            \
            _Pragma("unroll")                                                  \
            for (int o = 16; o > 0; o >>= 1) {                                 \
                s0 += __shfl_xor_sync(0xffffffffu, s0, o);                     \
                s1 += __shfl_xor_sync(0xffffffffu, s1, o);                     \
            }                                                                  \
            float c0 = __fdividef(e0, s0);                                     \
            float c1 = __fdividef(e1, s1);                                     \
            u64 c0P, c1P;                                                      \
            PACK2(c0P, c0); PACK2(c1P, c1);                                    \
            FMA2(p00, c0P, ua0, p00); FMA2(p01, c0P, ub0, p01);                \
            FMA2(p02, c0P, ua1, p02); FMA2(p03, c0P, ub1, p03);                \
            FMA2(p04, c0P, ua2, p04); FMA2(p05, c0P, ub2, p05);                \
            FMA2(p06, c0P, ua3, p06); FMA2(p07, c0P, ub3, p07);                \
            FMA2(p10, c1P, za0, p10); FMA2(p11, c1P, zb0, p11);                \
            FMA2(p12, c1P, za1, p12); FMA2(p13, c1P, zb1, p13);                \
            FMA2(p14, c1P, za2, p14); FMA2(p15, c1P, zb2, p15);                \
            FMA2(p16, c1P, za3, p16); FMA2(p17, c1P, zb3, p17);                \
        }                                                                      \
    }

#define STORE_ACC                                                              \
    {                                                                          \
        int base = ((wp << 5) + lane) << 2;                                    \
        ulonglong2 t;                                                          \
        t.x = p00; t.y = p01; vbufp[base + 0] = t;                             \
        t.x = p02; t.y = p03; vbufp[base + 1] = t;                             \
        t.x = p04; t.y = p05; vbufp[base + 2] = t;                             \
        t.x = p06; t.y = p07; vbufp[base + 3] = t;                             \
        t.x = p10; t.y = p11; vbufp[VB1 + base + 0] = t;                       \
        t.x = p12; t.y = p13; vbufp[VB1 + base + 1] = t;                       \
        t.x = p14; t.y = p15; vbufp[VB1 + base + 2] = t;                       \
        t.x = p16; t.y = p17; vbufp[VB1 + base + 3] = t;                       \
    }

    // ================= PASS B: r1, c1, accumulate ========================
    {
        p00 = p01 = p02 = p03 = p04 = p05 = p06 = p07 = 0;
        p10 = p11 = p12 = p13 = p14 = p15 = p16 = p17 = 0;
        ROUTING_PASS_LOOP
        STORE_ACC
    }
    __syncthreads();
    if (tid < 256) {
        int t = tid & 127, pp = tid >> 7;
        int C = t >> 2;
        int off = pp * VB1;
        float4 acc = vbufv[off + t];
        #pragma unroll
        for (int k = 1; k < NW; k++) {
            float4 u = vbufv[off + (k << 7) + t];
            acc.x += u.x; acc.y += u.y; acc.z += u.z; acc.w += u.w;
        }
        float f = invd[(pp << 5) + C];
        acc.x *= f; acc.y *= f; acc.z *= f; acc.w *= f;
        float s = acc.x * acc.x + acc.y * acc.y + acc.z * acc.z + acc.w * acc.w;
        s += __shfl_xor_sync(0xffffffffu, s, 1);
        s += __shfl_xor_sync(0xffffffffu, s, 2);
        float nrm = __fsqrt_rn(s + EPSF);
        float g = 1.f / (1.f + nrm);
        acc.x *= g; acc.y *= g; acc.z *= g; acc.w *= g;
        vcurv[(pp << 7) + t] = acc;   // v1
    }
    __syncthreads();

    // v <- v0 + v1 per position (linearity of r)
    {
        ulonglong2 t0 = vcurp[(lane << 2) + 0];
        ulonglong2 t1 = vcurp[(lane << 2) + 1];
        ulonglong2 t2 = vcurp[(lane << 2) + 2];
        ulonglong2 t3 = vcurp[(lane << 2) + 3];
        ADD2(A0, A0, t0.x); ADD2(A1, A1, t0.y);
        ADD2(A2, A2, t1.x); ADD2(A3, A3, t1.y);
        ADD2(A4, A4, t2.x); ADD2(A5, A5, t2.y);
        ADD2(A6, A6, t3.x); ADD2(A7, A7, t3.y);
        t0 = vcurp[128 + (lane << 2) + 0];
        t1 = vcurp[128 + (lane << 2) + 1];
        t2 = vcurp[128 + (lane << 2) + 2];
        t3 = vcurp[128 + (lane << 2) + 3];
        ADD2(B0, B0, t0.x); ADD2(B1, B1, t0.y);
        ADD2(B2, B2, t1.x); ADD2(B3, B3, t1.y);
        ADD2(B4, B4, t2.x); ADD2(B5, B5, t2.y);
        ADD2(B6, B6, t3.x); ADD2(B7, B7, t3.y);
    }

    // ================= PASS C: r2, c2, accumulate, output ================
    {
        p00 = p01 = p02 = p03 = p04 = p05 = p06 = p07 = 0;
        p10 = p11 = p12 = p13 = p14 = p15 = p16 = p17 = 0;
        ROUTING_PASS_LOOP
        STORE_ACC
    }
    __syncthreads();
    if (tid < 256) {
        int t = tid & 127, pp = tid >> 7;
        int C = t >> 2, q = t & 3;
        int off = pp * VB1;
        float4 acc = vbufv[off + t];
        #pragma unroll
        for (int k = 1; k < NW; k++) {
            float4 u = vbufv[off + (k << 7) + t];
            acc.x += u.x; acc.y += u.y; acc.z += u.z; acc.w += u.w;
        }
        float f = invd[(pp << 5) + C];
        acc.x *= f; acc.y *= f; acc.z *= f; acc.w *= f;
        float s = acc.x * acc.x + acc.y * acc.y + acc.z * acc.z + acc.w * acc.w;
        s += __shfl_xor_sync(0xffffffffu, s, 1);
        s += __shfl_xor_sync(0xffffffffu, s, 2);
        float nrm = __fsqrt_rn(s + EPSF);
        float g = 1.f / (1.f + nrm);
        acc.x *= g; acc.y *= g; acc.z *= g; acc.w *= g;   // v2 (p_out)
        float s2 = acc.x * acc.x + acc.y * acc.y + acc.z * acc.z + acc.w * acc.w;
        s2 += __shfl_xor_sync(0xffffffffu, s2, 1);
        s2 += __shfl_xor_sync(0xffffffffu, s2, 2);
        float aout = __fsqrt_rn(s2 + EPSF);               // a_out = safe_norm(v2)
        int pos = pos0 + pp;
        int b = pos >> 6, hw = pos & 63;
        int basep = (((b * 32 + C) * 16 + (q << 2)) << 6) + hw;
        out[basep]       = acc.x;
        out[basep + 64]  = acc.y;
        out[basep + 128] = acc.z;
        out[basep + 192] = acc.w;
        if (q == 0)
            out[AOUT_BASE + ((b * 32 + C) << 6) + hw] = aout;
    }
}

extern "C" void kernel_launch(void* const* d_in, const int* in_sizes, int n_in,
                              void* d_out, int out_size) {
    (void)out_size;
    // Resolve inputs BY SIZE — immune to metadata ordering.
    const float* x  = nullptr;
    const float* Wg = nullptr;
    for (int i = 0; i < n_in; i++) {
        if (in_sizes[i] == 524288)      x  = (const float*)d_in[i];
        else if (in_sizes[i] == 147456) Wg = (const float*)d_in[i];
    }
    float* out = (float*)d_out;

    transpose_W_kernel<<<(288 * 16 * 32 + 255) / 256, 256>>>(Wg);

    const size_t smem_bytes = SMEM_FLOATS * sizeof(float);
    cudaFuncSetAttribute(convcaps_kernel,
                         cudaFuncAttributeMaxDynamicSharedMemorySize,
                         (int)smem_bytes);
    convcaps_kernel<<<128, 384, smem_bytes>>>(x, out);
}